// round 1
// baseline (speedup 1.0000x reference)
#include <cuda_runtime.h>
#include <cuda_bf16.h>
#include <math.h>

// ---------------------------------------------------------------------------
// SwinBlock: shift -> window -> LN1 -> QKV -> MHA(49 tok, 6 heads, hd=32)
//            -> proj -> unshift -> LN2 -> MLP(192->768->192, gelu) + residual
// B=32, H=W=56, C=192, WS=7, SS=3  => 2048 windows, 100352 tokens
// ---------------------------------------------------------------------------

#define TOK     100352          // B * H * W
#define CDIM    192
#define HIDDEN  768
#define QKVDIM  576
#define NWIN    2048
#define NHEAD   6
#define HD      32
#define WN      49              // tokens per window

// scratch (device globals: no allocation allowed in kernel_launch)
__device__ float g_xn  [ (size_t)TOK * CDIM   ];  // xn1, reused as xn2
__device__ float g_qkv [ (size_t)TOK * HIDDEN ];  // qkv (576 cols), reused as mlp hidden (768)
__device__ float g_attn[ (size_t)TOK * CDIM   ];  // attention out, window layout
__device__ float g_xa  [ (size_t)TOK * CDIM   ];  // attention result, natural layout

// window-row -> natural token index (same map for gather & scatter:
// shifted[h_s] = x[(h_s+3)%56]  and  result[(h_s+3)%56] = out[h_s])
__device__ __forceinline__ int nat_index(int r) {
    int widx = r / WN, n = r % WN;
    int b  = widx >> 6, wi = widx & 63;
    int hs = (wi >> 3) * 7 + n / 7;
    int ws = (wi & 7)  * 7 + n % 7;
    int h = hs + 3; if (h >= 56) h -= 56;
    int w = ws + 3; if (w >= 56) w -= 56;
    return b * 3136 + h * 56 + w;
}

// ---------------------------------------------------------------------------
// LayerNorm: one warp per token (C=192 -> 6 floats per lane)
// gather=1: output row r (window layout) reads natural token nat_index(r)
// ---------------------------------------------------------------------------
__global__ __launch_bounds__(256) void ln_kernel(
    const float* __restrict__ x, const float* __restrict__ g,
    const float* __restrict__ be, float* __restrict__ out, int gather)
{
    int r = (blockIdx.x * blockDim.x + threadIdx.x) >> 5;
    if (r >= TOK) return;
    int lane = threadIdx.x & 31;
    int src = gather ? nat_index(r) : r;
    const float* p = x + (size_t)src * CDIM;
    float v[6]; float s = 0.f, sq = 0.f;
#pragma unroll
    for (int i = 0; i < 6; i++) {
        v[i] = p[lane + 32 * i];
        s += v[i]; sq += v[i] * v[i];
    }
#pragma unroll
    for (int o = 16; o > 0; o >>= 1) {
        s  += __shfl_xor_sync(0xffffffffu, s,  o);
        sq += __shfl_xor_sync(0xffffffffu, sq, o);
    }
    float mean = s * (1.f / CDIM);
    float var  = sq * (1.f / CDIM) - mean * mean;
    float rstd = rsqrtf(var + 1e-5f);
    float* q = out + (size_t)r * CDIM;
#pragma unroll
    for (int i = 0; i < 6; i++) {
        int c = lane + 32 * i;
        q[c] = (v[i] - mean) * rstd * g[c] + be[c];
    }
}

// ---------------------------------------------------------------------------
// Generic fp32 GEMM:  C[M,N] = A[M,K] @ B[K,N] (+bias, epilogue variants)
// Tile 128x64xBK16, 256 threads, 8x4 micro-tile. All dims divide exactly.
// ---------------------------------------------------------------------------
#define BM 128
#define BN 64
#define BK 16

enum { EPI_BIAS = 0, EPI_PROJ = 1, EPI_GELU = 2, EPI_RES = 3 };

__device__ __forceinline__ float gelu_exact(float v) {
    return 0.5f * v * (1.0f + erff(v * 0.70710678118654752f));
}

template<int EPI>
__global__ __launch_bounds__(256) void gemm_kernel(
    const float* __restrict__ A, const float* __restrict__ B,
    const float* __restrict__ bias, float* __restrict__ C,
    const float* __restrict__ res, int M, int N, int K)
{
    __shared__ float As[BK][BM];
    __shared__ float Bs[BK][BN];

    const int tid = threadIdx.x;
    const int m0 = blockIdx.y * BM;
    const int n0 = blockIdx.x * BN;
    const int ty = tid >> 4;        // 0..15 -> rows ty*8..+7
    const int tx = tid & 15;        // 0..15 -> cols tx*4..+3

    // load indexing
    const int arow = tid >> 2;      // 0..63
    const int ac4  = tid & 3;       // 0..3  (k-subchunk of 4)
    const int brow = tid >> 4;      // 0..15
    const int bc4  = tid & 15;      // 0..15 (n-subchunk of 4)

    float acc[8][4];
#pragma unroll
    for (int i = 0; i < 8; i++)
#pragma unroll
        for (int j = 0; j < 4; j++) acc[i][j] = 0.f;

    for (int k0 = 0; k0 < K; k0 += BK) {
        float4 a0 = *(const float4*)(A + (size_t)(m0 + arow)      * K + k0 + ac4 * 4);
        float4 a1 = *(const float4*)(A + (size_t)(m0 + arow + 64) * K + k0 + ac4 * 4);
        float4 b0 = *(const float4*)(B + (size_t)(k0 + brow) * N + n0 + bc4 * 4);

        As[ac4*4+0][arow] = a0.x; As[ac4*4+1][arow] = a0.y;
        As[ac4*4+2][arow] = a0.z; As[ac4*4+3][arow] = a0.w;
        As[ac4*4+0][arow+64] = a1.x; As[ac4*4+1][arow+64] = a1.y;
        As[ac4*4+2][arow+64] = a1.z; As[ac4*4+3][arow+64] = a1.w;
        *(float4*)&Bs[brow][bc4 * 4] = b0;
        __syncthreads();

#pragma unroll
        for (int kk = 0; kk < BK; kk++) {
            float4 aA = *(const float4*)&As[kk][ty * 8];
            float4 aB = *(const float4*)&As[kk][ty * 8 + 4];
            float4 bb = *(const float4*)&Bs[kk][tx * 4];
            float ar[8] = {aA.x, aA.y, aA.z, aA.w, aB.x, aB.y, aB.z, aB.w};
            float br[4] = {bb.x, bb.y, bb.z, bb.w};
#pragma unroll
            for (int i = 0; i < 8; i++)
#pragma unroll
                for (int j = 0; j < 4; j++)
                    acc[i][j] += ar[i] * br[j];
        }
        __syncthreads();
    }

    float bv[4];
#pragma unroll
    for (int j = 0; j < 4; j++) bv[j] = bias[n0 + tx * 4 + j];

#pragma unroll
    for (int i = 0; i < 8; i++) {
        int m = m0 + ty * 8 + i;
        size_t orow;
        if (EPI == EPI_PROJ) orow = (size_t)nat_index(m) * N;   // scatter to natural layout
        else                 orow = (size_t)m * N;
#pragma unroll
        for (int j = 0; j < 4; j++) {
            int n = n0 + tx * 4 + j;
            float v = acc[i][j] + bv[j];
            if (EPI == EPI_GELU) v = gelu_exact(v);
            if (EPI == EPI_RES)  v += res[(size_t)m * N + n];
            C[orow + n] = v;
        }
    }
}

// ---------------------------------------------------------------------------
// Attention: one block per (window, head). QKV/S resident in smem.
// ---------------------------------------------------------------------------
__global__ __launch_bounds__(128) void attn_kernel(
    const float* __restrict__ qkv, float* __restrict__ out)
{
    const int widx = blockIdx.x;
    const int head = blockIdx.y;
    __shared__ float Q[WN][33], K[WN][33], V[WN][33], S[WN][50];
    const int tid = threadIdx.x;

    for (int t = tid; t < WN * HD; t += 128) {
        int n = t >> 5, d = t & 31;
        const float* base = qkv + (size_t)(widx * WN + n) * QKVDIM + head * HD + d;
        Q[n][d] = base[0];
        K[n][d] = base[CDIM];
        V[n][d] = base[2 * CDIM];
    }
    __syncthreads();

    const float scale = 0.17677669529663687f;  // 1/sqrt(32)
    for (int t = tid; t < WN * WN; t += 128) {
        int i = t / WN, j = t % WN;
        float s = 0.f;
#pragma unroll
        for (int d = 0; d < HD; d++) s += Q[i][d] * K[j][d];
        S[i][j] = s * scale;
    }
    __syncthreads();

    const int warp = tid >> 5, lane = tid & 31;
    for (int i = warp; i < WN; i += 4) {
        float v0 = S[i][lane];
        float v1 = (lane < 17) ? S[i][lane + 32] : -1e30f;
        float m = fmaxf(v0, v1);
#pragma unroll
        for (int o = 16; o > 0; o >>= 1) m = fmaxf(m, __shfl_xor_sync(0xffffffffu, m, o));
        float e0 = __expf(v0 - m);
        float e1 = (lane < 17) ? __expf(v1 - m) : 0.f;
        float s = e0 + e1;
#pragma unroll
        for (int o = 16; o > 0; o >>= 1) s += __shfl_xor_sync(0xffffffffu, s, o);
        float inv = 1.f / s;
        S[i][lane] = e0 * inv;
        if (lane < 17) S[i][lane + 32] = e1 * inv;
    }
    __syncthreads();

    for (int t = tid; t < WN * HD; t += 128) {
        int i = t >> 5, d = t & 31;
        float acc = 0.f;
#pragma unroll
        for (int j = 0; j < WN; j++) acc += S[i][j] * V[j][d];
        out[(size_t)(widx * WN + i) * CDIM + head * HD + d] = acc;
    }
}

// ---------------------------------------------------------------------------
// Launch
// ---------------------------------------------------------------------------
extern "C" void kernel_launch(void* const* d_in, const int* in_sizes, int n_in,
                              void* d_out, int out_size)
{
    const float* x      = (const float*)d_in[0];
    const float* qkv_w  = (const float*)d_in[1];
    const float* qkv_b  = (const float*)d_in[2];
    const float* proj_w = (const float*)d_in[3];
    const float* proj_b = (const float*)d_in[4];
    const float* g1     = (const float*)d_in[5];
    const float* be1    = (const float*)d_in[6];
    const float* g2     = (const float*)d_in[7];
    const float* be2    = (const float*)d_in[8];
    const float* w1     = (const float*)d_in[9];
    const float* b1     = (const float*)d_in[10];
    const float* w2     = (const float*)d_in[11];
    const float* b2     = (const float*)d_in[12];
    float* out = (float*)d_out;

    float *xn, *qkvbuf, *attnbuf, *xa;
    cudaGetSymbolAddress((void**)&xn,      g_xn);
    cudaGetSymbolAddress((void**)&qkvbuf,  g_qkv);
    cudaGetSymbolAddress((void**)&attnbuf, g_attn);
    cudaGetSymbolAddress((void**)&xa,      g_xa);

    const int lnBlocks = (TOK * 32) / 256;   // 12544

    // 1) shift+window gather + LN1  -> xn (window layout)
    ln_kernel<<<lnBlocks, 256>>>(x, g1, be1, xn, 1);

    // 2) QKV GEMM [100352,192]x[192,576]
    gemm_kernel<EPI_BIAS><<<dim3(QKVDIM / BN, TOK / BM), 256>>>(
        xn, qkv_w, qkv_b, qkvbuf, nullptr, TOK, QKVDIM, CDIM);

    // 3) windowed MHA
    attn_kernel<<<dim3(NWIN, NHEAD), 128>>>(qkvbuf, attnbuf);

    // 4) proj GEMM + scatter back to natural layout -> xa
    gemm_kernel<EPI_PROJ><<<dim3(CDIM / BN, TOK / BM), 256>>>(
        attnbuf, proj_w, proj_b, xa, nullptr, TOK, CDIM, CDIM);

    // 5) LN2 -> xn (reuse)
    ln_kernel<<<lnBlocks, 256>>>(xa, g2, be2, xn, 0);

    // 6) MLP fc1 + exact GELU -> qkvbuf (reuse, 768 cols)
    gemm_kernel<EPI_GELU><<<dim3(HIDDEN / BN, TOK / BM), 256>>>(
        xn, w1, b1, qkvbuf, nullptr, TOK, HIDDEN, CDIM);

    // 7) MLP fc2 + bias + residual(xa) -> d_out
    gemm_kernel<EPI_RES><<<dim3(CDIM / BN, TOK / BM), 256>>>(
        qkvbuf, w2, b2, out, xa, TOK, CDIM, HIDDEN);
}

// round 2
// speedup vs baseline: 1.9815x; 1.9815x over previous
#include <cuda_runtime.h>
#include <cuda_bf16.h>
#include <math.h>
#include <stdint.h>

// ---------------------------------------------------------------------------
// SwinBlock: shift -> window -> LN1 -> QKV -> MHA(49 tok, 6 heads, hd=32)
//            -> proj -> unshift -> LN2 -> MLP(192->768->192, gelu) + residual
// B=32, H=W=56, C=192, WS=7, SS=3  => 2048 windows, 100352 tokens
// GEMMs on tensor cores (tf32 mma.sync), fused epilogues.
// ---------------------------------------------------------------------------

#define TOK     100352
#define CDIM    192
#define HIDDEN  768
#define QKVDIM  576
#define NWIN    2048
#define NHEAD   6
#define HD      32
#define WN      49

__device__ float g_xn  [ (size_t)TOK * CDIM   ];
__device__ float g_qkv [ (size_t)TOK * HIDDEN ];
__device__ float g_attn[ (size_t)TOK * CDIM   ];
__device__ float g_xa  [ (size_t)TOK * CDIM   ];

__device__ __forceinline__ int nat_index(int r) {
    int widx = r / WN, n = r % WN;
    int b  = widx >> 6, wi = widx & 63;
    int hs = (wi >> 3) * 7 + n / 7;
    int ws = (wi & 7)  * 7 + n % 7;
    int h = hs + 3; if (h >= 56) h -= 56;
    int w = ws + 3; if (w >= 56) w -= 56;
    return b * 3136 + h * 56 + w;
}

// ---------------------------------------------------------------------------
// LayerNorm: one warp per token
// ---------------------------------------------------------------------------
__global__ __launch_bounds__(256) void ln_kernel(
    const float* __restrict__ x, const float* __restrict__ g,
    const float* __restrict__ be, float* __restrict__ out, int gather)
{
    int r = (blockIdx.x * blockDim.x + threadIdx.x) >> 5;
    if (r >= TOK) return;
    int lane = threadIdx.x & 31;
    int src = gather ? nat_index(r) : r;
    const float* p = x + (size_t)src * CDIM;
    float v[6]; float s = 0.f, sq = 0.f;
#pragma unroll
    for (int i = 0; i < 6; i++) {
        v[i] = p[lane + 32 * i];
        s += v[i]; sq += v[i] * v[i];
    }
#pragma unroll
    for (int o = 16; o > 0; o >>= 1) {
        s  += __shfl_xor_sync(0xffffffffu, s,  o);
        sq += __shfl_xor_sync(0xffffffffu, sq, o);
    }
    float mean = s * (1.f / CDIM);
    float var  = sq * (1.f / CDIM) - mean * mean;
    float rstd = rsqrtf(var + 1e-5f);
    float* q = out + (size_t)r * CDIM;
#pragma unroll
    for (int i = 0; i < 6; i++) {
        int c = lane + 32 * i;
        q[c] = (v[i] - mean) * rstd * g[c] + be[c];
    }
}

// ---------------------------------------------------------------------------
// tf32 tensor-core GEMM:  C[M,N] = A[M,K] @ B[K,N] (+bias / epilogues)
// Tile 128x64x16, 256 thr (8 warps: 4 along M x 2 along N, warp tile 32x32),
// mma.sync m16n8k8, cp.async double buffer.
// M % 128 == 0, N % 64 == 0, K % 16 == 0 (guaranteed by shapes here).
// ---------------------------------------------------------------------------
#define AP 20    // A smem row pitch (floats): conflict-free A-frag LDS
#define BP 72    // B smem row pitch (floats): conflict-free B-frag LDS

enum { EPI_BIAS = 0, EPI_PROJ = 1, EPI_GELU = 2, EPI_RES = 3 };

__device__ __forceinline__ float gelu_exact(float v) {
    return 0.5f * v * (1.0f + erff(v * 0.70710678118654752f));
}

#define CPA16(dst, src) \
    asm volatile("cp.async.cg.shared.global [%0], [%1], 16;" :: "r"(dst), "l"(src))
#define F2TF(u, f) \
    asm volatile("cvt.rna.tf32.f32 %0, %1;" : "=r"(u) : "f"(f))
#define MMA_TF32(c, a, b) \
    asm volatile("mma.sync.aligned.m16n8k8.row.col.f32.tf32.tf32.f32 " \
        "{%0,%1,%2,%3},{%4,%5,%6,%7},{%8,%9},{%0,%1,%2,%3};" \
        : "+f"(c[0]), "+f"(c[1]), "+f"(c[2]), "+f"(c[3]) \
        : "r"(a[0]), "r"(a[1]), "r"(a[2]), "r"(a[3]), "r"(b[0]), "r"(b[1]))

template<int EPI>
__global__ __launch_bounds__(256) void gemm_tc(
    const float* __restrict__ A, const float* __restrict__ B,
    const float* __restrict__ bias, float* __restrict__ C,
    const float* __restrict__ res, int M, int N, int K)
{
    __shared__ float As[2][128 * AP];
    __shared__ float Bs[2][16 * BP];

    const int tid  = threadIdx.x;
    const int lane = tid & 31, warp = tid >> 5;
    const int wm = (warp & 3) * 32;       // warp M offset within tile
    const int wn = (warp >> 2) * 32;      // warp N offset within tile
    const int m0 = blockIdx.y * 128, n0 = blockIdx.x * 64;

    // loader mapping
    const int ar  = tid >> 2;             // A row 0..63 (and +64)
    const int ac  = (tid & 3) * 4;        // A col 0..12
    const int bkr = tid >> 4;             // B k-row 0..15
    const int bc  = (tid & 15) * 4;       // B col 0..60

    const float* Ag0 = A + (size_t)(m0 + ar) * K + ac;
    const float* Ag1 = Ag0 + (size_t)64 * K;
    const float* Bg  = B + (size_t)bkr * N + n0 + bc;

    const uint32_t sa0 = (uint32_t)__cvta_generic_to_shared(&As[0][ar * AP + ac]);
    const uint32_t sa1 = (uint32_t)__cvta_generic_to_shared(&As[0][(ar + 64) * AP + ac]);
    const uint32_t sb  = (uint32_t)__cvta_generic_to_shared(&Bs[0][bkr * BP + bc]);
    const uint32_t ASTB = sizeof(float) * 128 * AP;
    const uint32_t BSTB = sizeof(float) * 16 * BP;

    float acc[2][4][4];
#pragma unroll
    for (int mi = 0; mi < 2; mi++)
#pragma unroll
        for (int ni = 0; ni < 4; ni++)
#pragma unroll
            for (int j = 0; j < 4; j++) acc[mi][ni][j] = 0.f;

    const int KT = K >> 4;

    // prefetch tile 0 into buffer 0
    CPA16(sa0, Ag0);
    CPA16(sa1, Ag1);
    CPA16(sb,  Bg);
    asm volatile("cp.async.commit_group;");

    for (int kt = 0; kt < KT; kt++) {
        const int buf = kt & 1;
        if (kt + 1 < KT) {
            const int nb = buf ^ 1;
            CPA16(sa0 + nb * ASTB, Ag0 + (kt + 1) * 16);
            CPA16(sa1 + nb * ASTB, Ag1 + (kt + 1) * 16);
            CPA16(sb  + nb * BSTB, Bg + (size_t)(kt + 1) * 16 * N);
            asm volatile("cp.async.commit_group;");
            asm volatile("cp.async.wait_group 1;");
        } else {
            asm volatile("cp.async.wait_group 0;");
        }
        __syncthreads();

        const float* as = As[buf];
        const float* bs = Bs[buf];
#pragma unroll
        for (int ks = 0; ks < 2; ks++) {
            uint32_t af[2][4], bf[4][2];
#pragma unroll
            for (int mi = 0; mi < 2; mi++) {
                const int r = wm + mi * 16 + (lane >> 2);
                const int c = ks * 8 + (lane & 3);
                float x0 = as[r * AP + c];
                float x1 = as[(r + 8) * AP + c];
                float x2 = as[r * AP + c + 4];
                float x3 = as[(r + 8) * AP + c + 4];
                F2TF(af[mi][0], x0); F2TF(af[mi][1], x1);
                F2TF(af[mi][2], x2); F2TF(af[mi][3], x3);
            }
#pragma unroll
            for (int ni = 0; ni < 4; ni++) {
                const int cc = wn + ni * 8 + (lane >> 2);
                const int r  = ks * 8 + (lane & 3);
                float y0 = bs[r * BP + cc];
                float y1 = bs[(r + 4) * BP + cc];
                F2TF(bf[ni][0], y0); F2TF(bf[ni][1], y1);
            }
#pragma unroll
            for (int mi = 0; mi < 2; mi++)
#pragma unroll
                for (int ni = 0; ni < 4; ni++)
                    MMA_TF32(acc[mi][ni], af[mi], bf[ni]);
        }
        __syncthreads();
    }

    // epilogue
#pragma unroll
    for (int mi = 0; mi < 2; mi++) {
#pragma unroll
        for (int h = 0; h < 2; h++) {
            const int row = m0 + wm + mi * 16 + (lane >> 2) + h * 8;
            size_t orow;
            if (EPI == EPI_PROJ) orow = (size_t)nat_index(row) * N;
            else                 orow = (size_t)row * N;
#pragma unroll
            for (int ni = 0; ni < 4; ni++) {
                const int cc = n0 + wn + ni * 8 + (lane & 3) * 2;
                float v0 = acc[mi][ni][2 * h + 0] + bias[cc];
                float v1 = acc[mi][ni][2 * h + 1] + bias[cc + 1];
                if (EPI == EPI_GELU) { v0 = gelu_exact(v0); v1 = gelu_exact(v1); }
                if (EPI == EPI_RES) {
                    v0 += res[(size_t)row * N + cc];
                    v1 += res[(size_t)row * N + cc + 1];
                }
                *(float2*)(C + orow + cc) = make_float2(v0, v1);
            }
        }
    }
}

// ---------------------------------------------------------------------------
// Attention: one block per (window, head). QKV/S resident in smem.
// ---------------------------------------------------------------------------
__global__ __launch_bounds__(128) void attn_kernel(
    const float* __restrict__ qkv, float* __restrict__ out)
{
    const int widx = blockIdx.x;
    const int head = blockIdx.y;
    __shared__ float Q[WN][33], K[WN][33], V[WN][33], S[WN][50];
    const int tid = threadIdx.x;

    for (int t = tid; t < WN * HD; t += 128) {
        int n = t >> 5, d = t & 31;
        const float* base = qkv + (size_t)(widx * WN + n) * QKVDIM + head * HD + d;
        Q[n][d] = base[0];
        K[n][d] = base[CDIM];
        V[n][d] = base[2 * CDIM];
    }
    __syncthreads();

    const float scale = 0.17677669529663687f;
    for (int t = tid; t < WN * WN; t += 128) {
        int i = t / WN, j = t % WN;
        float s = 0.f;
#pragma unroll
        for (int d = 0; d < HD; d++) s += Q[i][d] * K[j][d];
        S[i][j] = s * scale;
    }
    __syncthreads();

    const int warp = tid >> 5, lane = tid & 31;
    for (int i = warp; i < WN; i += 4) {
        float v0 = S[i][lane];
        float v1 = (lane < 17) ? S[i][lane + 32] : -1e30f;
        float m = fmaxf(v0, v1);
#pragma unroll
        for (int o = 16; o > 0; o >>= 1) m = fmaxf(m, __shfl_xor_sync(0xffffffffu, m, o));
        float e0 = __expf(v0 - m);
        float e1 = (lane < 17) ? __expf(v1 - m) : 0.f;
        float s = e0 + e1;
#pragma unroll
        for (int o = 16; o > 0; o >>= 1) s += __shfl_xor_sync(0xffffffffu, s, o);
        float inv = 1.f / s;
        S[i][lane] = e0 * inv;
        if (lane < 17) S[i][lane + 32] = e1 * inv;
    }
    __syncthreads();

    for (int t = tid; t < WN * HD; t += 128) {
        int i = t >> 5, d = t & 31;
        float acc = 0.f;
#pragma unroll
        for (int j = 0; j < WN; j++) acc += S[i][j] * V[j][d];
        out[(size_t)(widx * WN + i) * CDIM + head * HD + d] = acc;
    }
}

// ---------------------------------------------------------------------------
// Launch
// ---------------------------------------------------------------------------
extern "C" void kernel_launch(void* const* d_in, const int* in_sizes, int n_in,
                              void* d_out, int out_size)
{
    const float* x      = (const float*)d_in[0];
    const float* qkv_w  = (const float*)d_in[1];
    const float* qkv_b  = (const float*)d_in[2];
    const float* proj_w = (const float*)d_in[3];
    const float* proj_b = (const float*)d_in[4];
    const float* g1     = (const float*)d_in[5];
    const float* be1    = (const float*)d_in[6];
    const float* g2     = (const float*)d_in[7];
    const float* be2    = (const float*)d_in[8];
    const float* w1     = (const float*)d_in[9];
    const float* b1     = (const float*)d_in[10];
    const float* w2     = (const float*)d_in[11];
    const float* b2     = (const float*)d_in[12];
    float* out = (float*)d_out;

    float *xn, *qkvbuf, *attnbuf, *xa;
    cudaGetSymbolAddress((void**)&xn,      g_xn);
    cudaGetSymbolAddress((void**)&qkvbuf,  g_qkv);
    cudaGetSymbolAddress((void**)&attnbuf, g_attn);
    cudaGetSymbolAddress((void**)&xa,      g_xa);

    const int lnBlocks = (TOK * 32) / 256;

    // 1) shift+window gather + LN1 -> xn (window layout)
    ln_kernel<<<lnBlocks, 256>>>(x, g1, be1, xn, 1);

    // 2) QKV GEMM [100352,192]x[192,576]
    gemm_tc<EPI_BIAS><<<dim3(QKVDIM / 64, TOK / 128), 256>>>(
        xn, qkv_w, qkv_b, qkvbuf, nullptr, TOK, QKVDIM, CDIM);

    // 3) windowed MHA
    attn_kernel<<<dim3(NWIN, NHEAD), 128>>>(qkvbuf, attnbuf);

    // 4) proj GEMM + scatter to natural layout -> xa
    gemm_tc<EPI_PROJ><<<dim3(CDIM / 64, TOK / 128), 256>>>(
        attnbuf, proj_w, proj_b, xa, nullptr, TOK, CDIM, CDIM);

    // 5) LN2 -> xn
    ln_kernel<<<lnBlocks, 256>>>(xa, g2, be2, xn, 0);

    // 6) MLP fc1 + exact GELU -> qkvbuf (768 cols)
    gemm_tc<EPI_GELU><<<dim3(HIDDEN / 64, TOK / 128), 256>>>(
        xn, w1, b1, qkvbuf, nullptr, TOK, HIDDEN, CDIM);

    // 7) MLP fc2 + bias + residual(xa) -> d_out
    gemm_tc<EPI_RES><<<dim3(CDIM / 64, TOK / 128), 256>>>(
        qkvbuf, w2, b2, out, xa, TOK, CDIM, HIDDEN);
}

// round 3
// speedup vs baseline: 2.2007x; 1.1106x over previous
#include <cuda_runtime.h>
#include <cuda_bf16.h>
#include <math.h>
#include <stdint.h>

// ---------------------------------------------------------------------------
// SwinBlock, tf32 tensor-core GEMMs with pre-rounded operands + 3-stage
// cp.async pipeline; vectorized windowed attention; fused shift/window maps.
// ---------------------------------------------------------------------------

#define TOK     100352
#define CDIM    192
#define HIDDEN  768
#define QKVDIM  576
#define NWIN    2048
#define NHEAD   6
#define HD      32
#define WN      49

__device__ float g_xn  [ (size_t)TOK * CDIM   ];
__device__ float g_qkv [ (size_t)TOK * HIDDEN ];
__device__ float g_attn[ (size_t)TOK * CDIM   ];
__device__ float g_xa  [ (size_t)TOK * CDIM   ];
// pre-rounded (tf32) weights
__device__ float g_wq [ CDIM * QKVDIM ];
__device__ float g_wp [ CDIM * CDIM   ];
__device__ float g_w1 [ CDIM * HIDDEN ];
__device__ float g_w2 [ HIDDEN * CDIM ];

#define F2TF(u, f) \
    asm volatile("cvt.rna.tf32.f32 %0, %1;" : "=r"(u) : "f"(f))

__device__ __forceinline__ float round_tf32(float f) {
    uint32_t u; F2TF(u, f); return __uint_as_float(u);
}

__device__ __forceinline__ int nat_index(int r) {
    int widx = r / WN, n = r % WN;
    int b  = widx >> 6, wi = widx & 63;
    int hs = (wi >> 3) * 7 + n / 7;
    int ws = (wi & 7)  * 7 + n % 7;
    int h = hs + 3; if (h >= 56) h -= 56;
    int w = ws + 3; if (w >= 56) w -= 56;
    return b * 3136 + h * 56 + w;
}

// ---------------------------------------------------------------------------
// tf32 rounding pass for weights (once per launch, tiny)
// ---------------------------------------------------------------------------
__global__ void wconv_kernel(const float* __restrict__ a, float* __restrict__ oa, int na,
                             const float* __restrict__ b, float* __restrict__ ob, int nb,
                             const float* __restrict__ c, float* __restrict__ oc, int nc,
                             const float* __restrict__ d, float* __restrict__ od, int nd)
{
    int i = blockIdx.x * blockDim.x + threadIdx.x;
    int stride = gridDim.x * blockDim.x;
    for (int t = i; t < na; t += stride) oa[t] = round_tf32(a[t]);
    for (int t = i; t < nb; t += stride) ob[t] = round_tf32(b[t]);
    for (int t = i; t < nc; t += stride) oc[t] = round_tf32(c[t]);
    for (int t = i; t < nd; t += stride) od[t] = round_tf32(d[t]);
}

// ---------------------------------------------------------------------------
// LayerNorm: one warp per token; output rounded to tf32 (feeds GEMM A)
// ---------------------------------------------------------------------------
__global__ __launch_bounds__(256) void ln_kernel(
    const float* __restrict__ x, const float* __restrict__ g,
    const float* __restrict__ be, float* __restrict__ out, int gather)
{
    int r = (blockIdx.x * blockDim.x + threadIdx.x) >> 5;
    if (r >= TOK) return;
    int lane = threadIdx.x & 31;
    int src = gather ? nat_index(r) : r;
    const float* p = x + (size_t)src * CDIM;
    float v[6]; float s = 0.f, sq = 0.f;
#pragma unroll
    for (int i = 0; i < 6; i++) {
        v[i] = p[lane + 32 * i];
        s += v[i]; sq += v[i] * v[i];
    }
#pragma unroll
    for (int o = 16; o > 0; o >>= 1) {
        s  += __shfl_xor_sync(0xffffffffu, s,  o);
        sq += __shfl_xor_sync(0xffffffffu, sq, o);
    }
    float mean = s * (1.f / CDIM);
    float var  = sq * (1.f / CDIM) - mean * mean;
    float rstd = rsqrtf(var + 1e-5f);
    float* q = out + (size_t)r * CDIM;
#pragma unroll
    for (int i = 0; i < 6; i++) {
        int c = lane + 32 * i;
        q[c] = round_tf32((v[i] - mean) * rstd * g[c] + be[c]);
    }
}

// ---------------------------------------------------------------------------
// tf32 tensor-core GEMM, operands PRE-ROUNDED to tf32 (no cvt inner loop).
// Tile 128x64x16, 256 thr (8 warps, warp tile 32x32), 3-stage cp.async ring.
// ---------------------------------------------------------------------------
#define AP 20
#define BP 72
#define STG 3

enum { EPI_BIAS = 0, EPI_PROJ = 1, EPI_GELU = 2, EPI_RES = 3 };

__device__ __forceinline__ float gelu_exact(float v) {
    return 0.5f * v * (1.0f + erff(v * 0.70710678118654752f));
}

#define CPA16(dst, src) \
    asm volatile("cp.async.cg.shared.global [%0], [%1], 16;" :: "r"(dst), "l"(src))
#define MMA_TF32(c, a, b) \
    asm volatile("mma.sync.aligned.m16n8k8.row.col.f32.tf32.tf32.f32 " \
        "{%0,%1,%2,%3},{%4,%5,%6,%7},{%8,%9},{%0,%1,%2,%3};" \
        : "+f"(c[0]), "+f"(c[1]), "+f"(c[2]), "+f"(c[3]) \
        : "r"(a[0]), "r"(a[1]), "r"(a[2]), "r"(a[3]), "r"(b[0]), "r"(b[1]))

template<int EPI>
__global__ __launch_bounds__(256) void gemm_tc(
    const float* __restrict__ A, const float* __restrict__ B,
    const float* __restrict__ bias, float* __restrict__ C,
    const float* __restrict__ res, int M, int N, int K)
{
    __shared__ float As[STG][128 * AP];
    __shared__ float Bs[STG][16 * BP];

    const int tid  = threadIdx.x;
    const int lane = tid & 31, warp = tid >> 5;
    const int wm = (warp & 3) * 32;
    const int wn = (warp >> 2) * 32;
    const int m0 = blockIdx.y * 128, n0 = blockIdx.x * 64;

    const int ar  = tid >> 2;
    const int ac  = (tid & 3) * 4;
    const int bkr = tid >> 4;
    const int bc  = (tid & 15) * 4;

    const float* Ag0 = A + (size_t)(m0 + ar) * K + ac;
    const float* Ag1 = Ag0 + (size_t)64 * K;
    const float* Bg  = B + (size_t)bkr * N + n0 + bc;

    const uint32_t sa0 = (uint32_t)__cvta_generic_to_shared(&As[0][ar * AP + ac]);
    const uint32_t sa1 = (uint32_t)__cvta_generic_to_shared(&As[0][(ar + 64) * AP + ac]);
    const uint32_t sb  = (uint32_t)__cvta_generic_to_shared(&Bs[0][bkr * BP + bc]);
    const uint32_t ASTB = sizeof(float) * 128 * AP;
    const uint32_t BSTB = sizeof(float) * 16 * BP;

    float acc[2][4][4];
#pragma unroll
    for (int mi = 0; mi < 2; mi++)
#pragma unroll
        for (int ni = 0; ni < 4; ni++)
#pragma unroll
            for (int j = 0; j < 4; j++) acc[mi][ni][j] = 0.f;

    const int KT = K >> 4;

    // prefetch tiles 0,1
#pragma unroll
    for (int s = 0; s < STG - 1; s++) {
        CPA16(sa0 + s * ASTB, Ag0 + s * 16);
        CPA16(sa1 + s * ASTB, Ag1 + s * 16);
        CPA16(sb  + s * BSTB, Bg + (size_t)s * 16 * N);
        asm volatile("cp.async.commit_group;");
    }

    for (int kt = 0; kt < KT; kt++) {
        if (kt + 2 < KT) {
            const int nb = (kt + 2) % STG;
            CPA16(sa0 + nb * ASTB, Ag0 + (kt + 2) * 16);
            CPA16(sa1 + nb * ASTB, Ag1 + (kt + 2) * 16);
            CPA16(sb  + nb * BSTB, Bg + (size_t)(kt + 2) * 16 * N);
        }
        asm volatile("cp.async.commit_group;");   // always (tail commits empty)
        asm volatile("cp.async.wait_group 2;");
        __syncthreads();

        const float* as = As[kt % STG];
        const float* bs = Bs[kt % STG];
#pragma unroll
        for (int ks = 0; ks < 2; ks++) {
            uint32_t af[2][4], bf[4][2];
#pragma unroll
            for (int mi = 0; mi < 2; mi++) {
                const int r = wm + mi * 16 + (lane >> 2);
                const int c = ks * 8 + (lane & 3);
                af[mi][0] = __float_as_uint(as[r * AP + c]);
                af[mi][1] = __float_as_uint(as[(r + 8) * AP + c]);
                af[mi][2] = __float_as_uint(as[r * AP + c + 4]);
                af[mi][3] = __float_as_uint(as[(r + 8) * AP + c + 4]);
            }
#pragma unroll
            for (int ni = 0; ni < 4; ni++) {
                const int cc = wn + ni * 8 + (lane >> 2);
                const int r  = ks * 8 + (lane & 3);
                bf[ni][0] = __float_as_uint(bs[r * BP + cc]);
                bf[ni][1] = __float_as_uint(bs[(r + 4) * BP + cc]);
            }
#pragma unroll
            for (int mi = 0; mi < 2; mi++)
#pragma unroll
                for (int ni = 0; ni < 4; ni++)
                    MMA_TF32(acc[mi][ni], af[mi], bf[ni]);
        }
        __syncthreads();
    }

    // epilogue
#pragma unroll
    for (int mi = 0; mi < 2; mi++) {
#pragma unroll
        for (int h = 0; h < 2; h++) {
            const int row = m0 + wm + mi * 16 + (lane >> 2) + h * 8;
            size_t orow;
            if (EPI == EPI_PROJ) orow = (size_t)nat_index(row) * N;
            else                 orow = (size_t)row * N;
#pragma unroll
            for (int ni = 0; ni < 4; ni++) {
                const int cc = n0 + wn + ni * 8 + (lane & 3) * 2;
                float v0 = acc[mi][ni][2 * h + 0] + bias[cc];
                float v1 = acc[mi][ni][2 * h + 1] + bias[cc + 1];
                if (EPI == EPI_GELU) {     // feeds fc2 A: round to tf32
                    v0 = round_tf32(gelu_exact(v0));
                    v1 = round_tf32(gelu_exact(v1));
                }
                if (EPI == EPI_RES) {
                    v0 += res[(size_t)row * N + cc];
                    v1 += res[(size_t)row * N + cc + 1];
                }
                *(float2*)(C + orow + cc) = make_float2(v0, v1);
            }
        }
    }
}

// ---------------------------------------------------------------------------
// Attention: one block per (window, head), float4-vectorized.
// Output rounded to tf32 (feeds proj GEMM A).
// ---------------------------------------------------------------------------
#define QP 36   // pitch (floats) for Q/K/V rows: 144B, 16B-aligned
__global__ __launch_bounds__(128) void attn_kernel(
    const float* __restrict__ qkv, float* __restrict__ out)
{
    const int widx = blockIdx.x;
    const int head = blockIdx.y;
    __shared__ float Q[WN * QP], K[WN * QP], V[WN * QP], S[WN][52];
    const int tid = threadIdx.x;

    // load Q/K/V: float4 per item
    for (int t = tid; t < WN * 8; t += 128) {
        int n = t >> 3, d4 = (t & 7) * 4;
        const float* base = qkv + (size_t)(widx * WN + n) * QKVDIM + head * HD + d4;
        *(float4*)&Q[n * QP + d4] = *(const float4*)(base);
        *(float4*)&K[n * QP + d4] = *(const float4*)(base + CDIM);
        *(float4*)&V[n * QP + d4] = *(const float4*)(base + 2 * CDIM);
    }
    __syncthreads();

    const float scale = 0.17677669529663687f;  // 1/sqrt(32)
    for (int t = tid; t < WN * WN; t += 128) {
        int i = t / WN, j = t % WN;
        float4 s4 = make_float4(0.f, 0.f, 0.f, 0.f);
#pragma unroll
        for (int dd = 0; dd < 8; dd++) {
            float4 q4 = *(const float4*)&Q[i * QP + dd * 4];
            float4 k4 = *(const float4*)&K[j * QP + dd * 4];
            s4.x += q4.x * k4.x; s4.y += q4.y * k4.y;
            s4.z += q4.z * k4.z; s4.w += q4.w * k4.w;
        }
        S[i][j] = (s4.x + s4.y + s4.z + s4.w) * scale;
    }
    __syncthreads();

    const int warp = tid >> 5, lane = tid & 31;
    for (int i = warp; i < WN; i += 4) {
        float v0 = S[i][lane];
        float v1 = (lane < 17) ? S[i][lane + 32] : -1e30f;
        float m = fmaxf(v0, v1);
#pragma unroll
        for (int o = 16; o > 0; o >>= 1) m = fmaxf(m, __shfl_xor_sync(0xffffffffu, m, o));
        float e0 = __expf(v0 - m);
        float e1 = (lane < 17) ? __expf(v1 - m) : 0.f;
        float s = e0 + e1;
#pragma unroll
        for (int o = 16; o > 0; o >>= 1) s += __shfl_xor_sync(0xffffffffu, s, o);
        float inv = 1.f / s;
        S[i][lane] = e0 * inv;
        if (lane < 17) S[i][lane + 32] = e1 * inv;
    }
    __syncthreads();

    // out = S @ V, float4 over d
    for (int t = tid; t < WN * 8; t += 128) {
        int i = t >> 3, d4 = (t & 7) * 4;
        float4 acc = make_float4(0.f, 0.f, 0.f, 0.f);
#pragma unroll
        for (int j = 0; j < WN; j++) {
            float s = S[i][j];
            float4 v4 = *(const float4*)&V[j * QP + d4];
            acc.x += s * v4.x; acc.y += s * v4.y;
            acc.z += s * v4.z; acc.w += s * v4.w;
        }
        float4 o4 = make_float4(round_tf32(acc.x), round_tf32(acc.y),
                                round_tf32(acc.z), round_tf32(acc.w));
        *(float4*)(out + (size_t)(widx * WN + i) * CDIM + head * HD + d4) = o4;
    }
}

// ---------------------------------------------------------------------------
// Launch
// ---------------------------------------------------------------------------
extern "C" void kernel_launch(void* const* d_in, const int* in_sizes, int n_in,
                              void* d_out, int out_size)
{
    const float* x      = (const float*)d_in[0];
    const float* qkv_w  = (const float*)d_in[1];
    const float* qkv_b  = (const float*)d_in[2];
    const float* proj_w = (const float*)d_in[3];
    const float* proj_b = (const float*)d_in[4];
    const float* g1     = (const float*)d_in[5];
    const float* be1    = (const float*)d_in[6];
    const float* g2     = (const float*)d_in[7];
    const float* be2    = (const float*)d_in[8];
    const float* w1     = (const float*)d_in[9];
    const float* b1     = (const float*)d_in[10];
    const float* w2     = (const float*)d_in[11];
    const float* b2     = (const float*)d_in[12];
    float* out = (float*)d_out;

    float *xn, *qkvbuf, *attnbuf, *xa, *wq, *wp, *wf1, *wf2;
    cudaGetSymbolAddress((void**)&xn,      g_xn);
    cudaGetSymbolAddress((void**)&qkvbuf,  g_qkv);
    cudaGetSymbolAddress((void**)&attnbuf, g_attn);
    cudaGetSymbolAddress((void**)&xa,      g_xa);
    cudaGetSymbolAddress((void**)&wq,      g_wq);
    cudaGetSymbolAddress((void**)&wp,      g_wp);
    cudaGetSymbolAddress((void**)&wf1,     g_w1);
    cudaGetSymbolAddress((void**)&wf2,     g_w2);

    const int lnBlocks = (TOK * 32) / 256;

    // 0) weights -> tf32 (tiny)
    wconv_kernel<<<432, 256>>>(qkv_w, wq, CDIM * QKVDIM,
                               proj_w, wp, CDIM * CDIM,
                               w1, wf1, CDIM * HIDDEN,
                               w2, wf2, HIDDEN * CDIM);

    // 1) shift+window gather + LN1 -> xn
    ln_kernel<<<lnBlocks, 256>>>(x, g1, be1, xn, 1);

    // 2) QKV GEMM
    gemm_tc<EPI_BIAS><<<dim3(QKVDIM / 64, TOK / 128), 256>>>(
        xn, wq, qkv_b, qkvbuf, nullptr, TOK, QKVDIM, CDIM);

    // 3) windowed MHA
    attn_kernel<<<dim3(NWIN, NHEAD), 128>>>(qkvbuf, attnbuf);

    // 4) proj GEMM + scatter -> xa
    gemm_tc<EPI_PROJ><<<dim3(CDIM / 64, TOK / 128), 256>>>(
        attnbuf, wp, proj_b, xa, nullptr, TOK, CDIM, CDIM);

    // 5) LN2 -> xn
    ln_kernel<<<lnBlocks, 256>>>(xa, g2, be2, xn, 0);

    // 6) MLP fc1 + GELU -> qkvbuf
    gemm_tc<EPI_GELU><<<dim3(HIDDEN / 64, TOK / 128), 256>>>(
        xn, wf1, b1, qkvbuf, nullptr, TOK, HIDDEN, CDIM);

    // 7) MLP fc2 + residual -> out
    gemm_tc<EPI_RES><<<dim3(CDIM / 64, TOK / 128), 256>>>(
        qkvbuf, wf2, b2, out, xa, TOK, CDIM, HIDDEN);
}

// round 4
// speedup vs baseline: 2.6068x; 1.1845x over previous
#include <cuda_runtime.h>
#include <cuda_bf16.h>
#include <math.h>
#include <stdint.h>

// ---------------------------------------------------------------------------
// SwinBlock. tf32 tensor-core GEMMs (pre-rounded operands, 3-stage cp.async)
// + tf32 tensor-core windowed attention (padded 64x56x32 / 64x32x56 mma).
// ---------------------------------------------------------------------------

#define TOK     100352
#define CDIM    192
#define HIDDEN  768
#define QKVDIM  576
#define NWIN    2048
#define NHEAD   6
#define HD      32
#define WN      49

__device__ float g_xn  [ (size_t)TOK * CDIM   ];
__device__ float g_qkv [ (size_t)TOK * HIDDEN ];
__device__ float g_attn[ (size_t)TOK * CDIM   ];
__device__ float g_xa  [ (size_t)TOK * CDIM   ];
__device__ float g_wq [ CDIM * QKVDIM ];
__device__ float g_wp [ CDIM * CDIM   ];
__device__ float g_w1 [ CDIM * HIDDEN ];
__device__ float g_w2 [ HIDDEN * CDIM ];

#define F2TF(u, f) \
    asm volatile("cvt.rna.tf32.f32 %0, %1;" : "=r"(u) : "f"(f))

__device__ __forceinline__ float round_tf32(float f) {
    uint32_t u; F2TF(u, f); return __uint_as_float(u);
}

__device__ __forceinline__ int nat_index(int r) {
    int widx = r / WN, n = r % WN;
    int b  = widx >> 6, wi = widx & 63;
    int hs = (wi >> 3) * 7 + n / 7;
    int ws = (wi & 7)  * 7 + n % 7;
    int h = hs + 3; if (h >= 56) h -= 56;
    int w = ws + 3; if (w >= 56) w -= 56;
    return b * 3136 + h * 56 + w;
}

#define MMA_TF32(c, a, b) \
    asm volatile("mma.sync.aligned.m16n8k8.row.col.f32.tf32.tf32.f32 " \
        "{%0,%1,%2,%3},{%4,%5,%6,%7},{%8,%9},{%0,%1,%2,%3};" \
        : "+f"(c[0]), "+f"(c[1]), "+f"(c[2]), "+f"(c[3]) \
        : "r"(a[0]), "r"(a[1]), "r"(a[2]), "r"(a[3]), "r"(b[0]), "r"(b[1]))

// ---------------------------------------------------------------------------
// tf32 rounding pass for weights
// ---------------------------------------------------------------------------
__global__ void wconv_kernel(const float* __restrict__ a, float* __restrict__ oa, int na,
                             const float* __restrict__ b, float* __restrict__ ob, int nb,
                             const float* __restrict__ c, float* __restrict__ oc, int nc,
                             const float* __restrict__ d, float* __restrict__ od, int nd)
{
    int i = blockIdx.x * blockDim.x + threadIdx.x;
    int stride = gridDim.x * blockDim.x;
    for (int t = i; t < na; t += stride) oa[t] = round_tf32(a[t]);
    for (int t = i; t < nb; t += stride) ob[t] = round_tf32(b[t]);
    for (int t = i; t < nc; t += stride) oc[t] = round_tf32(c[t]);
    for (int t = i; t < nd; t += stride) od[t] = round_tf32(d[t]);
}

// ---------------------------------------------------------------------------
// LayerNorm: one warp per token; output rounded to tf32
// ---------------------------------------------------------------------------
__global__ __launch_bounds__(256) void ln_kernel(
    const float* __restrict__ x, const float* __restrict__ g,
    const float* __restrict__ be, float* __restrict__ out, int gather)
{
    int r = (blockIdx.x * blockDim.x + threadIdx.x) >> 5;
    if (r >= TOK) return;
    int lane = threadIdx.x & 31;
    int src = gather ? nat_index(r) : r;
    const float* p = x + (size_t)src * CDIM;
    float v[6]; float s = 0.f, sq = 0.f;
#pragma unroll
    for (int i = 0; i < 6; i++) {
        v[i] = p[lane + 32 * i];
        s += v[i]; sq += v[i] * v[i];
    }
#pragma unroll
    for (int o = 16; o > 0; o >>= 1) {
        s  += __shfl_xor_sync(0xffffffffu, s,  o);
        sq += __shfl_xor_sync(0xffffffffu, sq, o);
    }
    float mean = s * (1.f / CDIM);
    float var  = sq * (1.f / CDIM) - mean * mean;
    float rstd = rsqrtf(var + 1e-5f);
    float* q = out + (size_t)r * CDIM;
#pragma unroll
    for (int i = 0; i < 6; i++) {
        int c = lane + 32 * i;
        q[c] = round_tf32((v[i] - mean) * rstd * g[c] + be[c]);
    }
}

// ---------------------------------------------------------------------------
// tf32 tensor-core GEMM (unchanged from round 3)
// ---------------------------------------------------------------------------
#define AP 20
#define BP 72
#define STG 3

enum { EPI_BIAS = 0, EPI_PROJ = 1, EPI_GELU = 2, EPI_RES = 3 };

__device__ __forceinline__ float gelu_exact(float v) {
    return 0.5f * v * (1.0f + erff(v * 0.70710678118654752f));
}

#define CPA16(dst, src) \
    asm volatile("cp.async.cg.shared.global [%0], [%1], 16;" :: "r"(dst), "l"(src))

template<int EPI>
__global__ __launch_bounds__(256) void gemm_tc(
    const float* __restrict__ A, const float* __restrict__ B,
    const float* __restrict__ bias, float* __restrict__ C,
    const float* __restrict__ res, int M, int N, int K)
{
    __shared__ float As[STG][128 * AP];
    __shared__ float Bs[STG][16 * BP];

    const int tid  = threadIdx.x;
    const int lane = tid & 31, warp = tid >> 5;
    const int wm = (warp & 3) * 32;
    const int wn = (warp >> 2) * 32;
    const int m0 = blockIdx.y * 128, n0 = blockIdx.x * 64;

    const int ar  = tid >> 2;
    const int ac  = (tid & 3) * 4;
    const int bkr = tid >> 4;
    const int bc  = (tid & 15) * 4;

    const float* Ag0 = A + (size_t)(m0 + ar) * K + ac;
    const float* Ag1 = Ag0 + (size_t)64 * K;
    const float* Bg  = B + (size_t)bkr * N + n0 + bc;

    const uint32_t sa0 = (uint32_t)__cvta_generic_to_shared(&As[0][ar * AP + ac]);
    const uint32_t sa1 = (uint32_t)__cvta_generic_to_shared(&As[0][(ar + 64) * AP + ac]);
    const uint32_t sb  = (uint32_t)__cvta_generic_to_shared(&Bs[0][bkr * BP + bc]);
    const uint32_t ASTB = sizeof(float) * 128 * AP;
    const uint32_t BSTB = sizeof(float) * 16 * BP;

    float acc[2][4][4];
#pragma unroll
    for (int mi = 0; mi < 2; mi++)
#pragma unroll
        for (int ni = 0; ni < 4; ni++)
#pragma unroll
            for (int j = 0; j < 4; j++) acc[mi][ni][j] = 0.f;

    const int KT = K >> 4;

#pragma unroll
    for (int s = 0; s < STG - 1; s++) {
        CPA16(sa0 + s * ASTB, Ag0 + s * 16);
        CPA16(sa1 + s * ASTB, Ag1 + s * 16);
        CPA16(sb  + s * BSTB, Bg + (size_t)s * 16 * N);
        asm volatile("cp.async.commit_group;");
    }

    for (int kt = 0; kt < KT; kt++) {
        if (kt + 2 < KT) {
            const int nb = (kt + 2) % STG;
            CPA16(sa0 + nb * ASTB, Ag0 + (kt + 2) * 16);
            CPA16(sa1 + nb * ASTB, Ag1 + (kt + 2) * 16);
            CPA16(sb  + nb * BSTB, Bg + (size_t)(kt + 2) * 16 * N);
        }
        asm volatile("cp.async.commit_group;");
        asm volatile("cp.async.wait_group 2;");
        __syncthreads();

        const float* as = As[kt % STG];
        const float* bs = Bs[kt % STG];
#pragma unroll
        for (int ks = 0; ks < 2; ks++) {
            uint32_t af[2][4], bf[4][2];
#pragma unroll
            for (int mi = 0; mi < 2; mi++) {
                const int r = wm + mi * 16 + (lane >> 2);
                const int c = ks * 8 + (lane & 3);
                af[mi][0] = __float_as_uint(as[r * AP + c]);
                af[mi][1] = __float_as_uint(as[(r + 8) * AP + c]);
                af[mi][2] = __float_as_uint(as[r * AP + c + 4]);
                af[mi][3] = __float_as_uint(as[(r + 8) * AP + c + 4]);
            }
#pragma unroll
            for (int ni = 0; ni < 4; ni++) {
                const int cc = wn + ni * 8 + (lane >> 2);
                const int r  = ks * 8 + (lane & 3);
                bf[ni][0] = __float_as_uint(bs[r * BP + cc]);
                bf[ni][1] = __float_as_uint(bs[(r + 4) * BP + cc]);
            }
#pragma unroll
            for (int mi = 0; mi < 2; mi++)
#pragma unroll
                for (int ni = 0; ni < 4; ni++)
                    MMA_TF32(acc[mi][ni], af[mi], bf[ni]);
        }
        __syncthreads();
    }

#pragma unroll
    for (int mi = 0; mi < 2; mi++) {
#pragma unroll
        for (int h = 0; h < 2; h++) {
            const int row = m0 + wm + mi * 16 + (lane >> 2) + h * 8;
            size_t orow;
            if (EPI == EPI_PROJ) orow = (size_t)nat_index(row) * N;
            else                 orow = (size_t)row * N;
#pragma unroll
            for (int ni = 0; ni < 4; ni++) {
                const int cc = n0 + wn + ni * 8 + (lane & 3) * 2;
                float v0 = acc[mi][ni][2 * h + 0] + bias[cc];
                float v1 = acc[mi][ni][2 * h + 1] + bias[cc + 1];
                if (EPI == EPI_GELU) {
                    v0 = round_tf32(gelu_exact(v0));
                    v1 = round_tf32(gelu_exact(v1));
                }
                if (EPI == EPI_RES) {
                    v0 += res[(size_t)row * N + cc];
                    v1 += res[(size_t)row * N + cc + 1];
                }
                *(float2*)(C + orow + cc) = make_float2(v0, v1);
            }
        }
    }
}

// ---------------------------------------------------------------------------
// Attention on tensor cores. One block per (window, head), 128 thr = 4 warps.
// Phase 1: S[64p x 56p] = Q[64p x 32] @ Kt[32 x 56p]   (M pad from 49, N pad)
// Phase 2: O[64p x 32]  = P[64p x 56p] @ V[56p x 32]
// P pad columns and V pad rows are zeroed => padding contributes exactly 0.
// Pad output rows are masked at the store.
// ---------------------------------------------------------------------------
#define ATQ 36   // Q pitch   (rows=64, cols=32)
#define ATK 72   // Kt pitch  (rows=32, cols=56)
#define ATS 60   // S pitch   (rows=64, cols=56)
#define ATV 40   // V pitch   (rows=56, cols=32)

__global__ __launch_bounds__(128) void attn_mma_kernel(
    const float* __restrict__ qkv, float* __restrict__ out)
{
    const int widx = blockIdx.x;
    const int head = blockIdx.y;
    __shared__ float Q [64 * ATQ];
    __shared__ float Kt[32 * ATK];
    __shared__ float S [64 * ATS];
    __shared__ float V [56 * ATV];

    const int tid = threadIdx.x;
    const int lane = tid & 31, warp = tid >> 5;
    const int wm = warp * 16;

    // zero V pad rows 49..55 (7 * ATV floats)
    for (int t = tid; t < 7 * ATV; t += 128) V[49 * ATV + t] = 0.f;

    // load Q/K/V (rounded to tf32). K stored transposed -> Kt[d][j].
    for (int t = tid; t < WN * 8; t += 128) {
        int n = t >> 3, d4 = (t & 7) * 4;
        const float* base = qkv + (size_t)(widx * WN + n) * QKVDIM + head * HD + d4;
        float4 q4 = *(const float4*)(base);
        float4 k4 = *(const float4*)(base + CDIM);
        float4 v4 = *(const float4*)(base + 2 * CDIM);
        *(float4*)&Q[n * ATQ + d4] = make_float4(round_tf32(q4.x), round_tf32(q4.y),
                                                 round_tf32(q4.z), round_tf32(q4.w));
        Kt[(d4 + 0) * ATK + n] = round_tf32(k4.x);
        Kt[(d4 + 1) * ATK + n] = round_tf32(k4.y);
        Kt[(d4 + 2) * ATK + n] = round_tf32(k4.z);
        Kt[(d4 + 3) * ATK + n] = round_tf32(k4.w);
        *(float4*)&V[n * ATV + d4] = make_float4(round_tf32(v4.x), round_tf32(v4.y),
                                                 round_tf32(v4.z), round_tf32(v4.w));
    }
    __syncthreads();

    // ---- Phase 1: S = Q @ Kt  (M=64 tile per warp: wm..wm+15; N=56; K=32)
    {
        float sacc[7][4];
#pragma unroll
        for (int ni = 0; ni < 7; ni++)
#pragma unroll
            for (int j = 0; j < 4; j++) sacc[ni][j] = 0.f;

#pragma unroll
        for (int ks = 0; ks < 4; ks++) {
            uint32_t a[4];
            const int r = wm + (lane >> 2);
            const int c = ks * 8 + (lane & 3);
            a[0] = __float_as_uint(Q[r * ATQ + c]);
            a[1] = __float_as_uint(Q[(r + 8) * ATQ + c]);
            a[2] = __float_as_uint(Q[r * ATQ + c + 4]);
            a[3] = __float_as_uint(Q[(r + 8) * ATQ + c + 4]);
#pragma unroll
            for (int ni = 0; ni < 7; ni++) {
                uint32_t b[2];
                const int cc = ni * 8 + (lane >> 2);
                const int rk = ks * 8 + (lane & 3);
                b[0] = __float_as_uint(Kt[rk * ATK + cc]);
                b[1] = __float_as_uint(Kt[(rk + 4) * ATK + cc]);
                MMA_TF32(sacc[ni], a, b);
            }
        }
        const float scale = 0.17677669529663687f;   // 1/sqrt(32)
        const int row = wm + (lane >> 2);
#pragma unroll
        for (int ni = 0; ni < 7; ni++) {
            const int col = ni * 8 + (lane & 3) * 2;
            *(float2*)&S[row * ATS + col]       = make_float2(sacc[ni][0] * scale, sacc[ni][1] * scale);
            *(float2*)&S[(row + 8) * ATS + col] = make_float2(sacc[ni][2] * scale, sacc[ni][3] * scale);
        }
    }
    __syncthreads();

    // ---- softmax over valid rows/cols; zero pad cols 49..55
    for (int i = warp; i < WN; i += 4) {
        float v0 = S[i * ATS + lane];
        float v1 = (lane < 17) ? S[i * ATS + 32 + lane] : -1e30f;
        float m = fmaxf(v0, v1);
#pragma unroll
        for (int o = 16; o > 0; o >>= 1) m = fmaxf(m, __shfl_xor_sync(0xffffffffu, m, o));
        float e0 = __expf(v0 - m);
        float e1 = (lane < 17) ? __expf(v1 - m) : 0.f;
        float s = e0 + e1;
#pragma unroll
        for (int o = 16; o > 0; o >>= 1) s += __shfl_xor_sync(0xffffffffu, s, o);
        float inv = 1.f / s;
        S[i * ATS + lane] = e0 * inv;
        if (lane < 17)               S[i * ATS + 32 + lane] = e1 * inv;
        else if (lane < 24)          S[i * ATS + 32 + lane] = 0.f;   // cols 49..55
    }
    __syncthreads();

    // ---- Phase 2: O = P @ V  (M=64; N=32; K=56)
    {
        float oacc[4][4];
#pragma unroll
        for (int ni = 0; ni < 4; ni++)
#pragma unroll
            for (int j = 0; j < 4; j++) oacc[ni][j] = 0.f;

#pragma unroll
        for (int ks = 0; ks < 7; ks++) {
            uint32_t a[4];
            const int r = wm + (lane >> 2);
            const int c = ks * 8 + (lane & 3);
            F2TF(a[0], S[r * ATS + c]);
            F2TF(a[1], S[(r + 8) * ATS + c]);
            F2TF(a[2], S[r * ATS + c + 4]);
            F2TF(a[3], S[(r + 8) * ATS + c + 4]);
#pragma unroll
            for (int ni = 0; ni < 4; ni++) {
                uint32_t b[2];
                const int cc = ni * 8 + (lane >> 2);
                const int rk = ks * 8 + (lane & 3);
                b[0] = __float_as_uint(V[rk * ATV + cc]);
                b[1] = __float_as_uint(V[(rk + 4) * ATV + cc]);
                MMA_TF32(oacc[ni], a, b);
            }
        }
#pragma unroll
        for (int h = 0; h < 2; h++) {
            const int row = wm + (lane >> 2) + h * 8;
            if (row < WN) {
                float* orow = out + (size_t)(widx * WN + row) * CDIM + head * HD;
#pragma unroll
                for (int ni = 0; ni < 4; ni++) {
                    const int col = ni * 8 + (lane & 3) * 2;
                    *(float2*)(orow + col) = make_float2(round_tf32(oacc[ni][2 * h + 0]),
                                                         round_tf32(oacc[ni][2 * h + 1]));
                }
            }
        }
    }
}

// ---------------------------------------------------------------------------
// Launch
// ---------------------------------------------------------------------------
extern "C" void kernel_launch(void* const* d_in, const int* in_sizes, int n_in,
                              void* d_out, int out_size)
{
    const float* x      = (const float*)d_in[0];
    const float* qkv_w  = (const float*)d_in[1];
    const float* qkv_b  = (const float*)d_in[2];
    const float* proj_w = (const float*)d_in[3];
    const float* proj_b = (const float*)d_in[4];
    const float* g1     = (const float*)d_in[5];
    const float* be1    = (const float*)d_in[6];
    const float* g2     = (const float*)d_in[7];
    const float* be2    = (const float*)d_in[8];
    const float* w1     = (const float*)d_in[9];
    const float* b1     = (const float*)d_in[10];
    const float* w2     = (const float*)d_in[11];
    const float* b2     = (const float*)d_in[12];
    float* out = (float*)d_out;

    float *xn, *qkvbuf, *attnbuf, *xa, *wq, *wp, *wf1, *wf2;
    cudaGetSymbolAddress((void**)&xn,      g_xn);
    cudaGetSymbolAddress((void**)&qkvbuf,  g_qkv);
    cudaGetSymbolAddress((void**)&attnbuf, g_attn);
    cudaGetSymbolAddress((void**)&xa,      g_xa);
    cudaGetSymbolAddress((void**)&wq,      g_wq);
    cudaGetSymbolAddress((void**)&wp,      g_wp);
    cudaGetSymbolAddress((void**)&wf1,     g_w1);
    cudaGetSymbolAddress((void**)&wf2,     g_w2);

    const int lnBlocks = (TOK * 32) / 256;

    wconv_kernel<<<432, 256>>>(qkv_w, wq, CDIM * QKVDIM,
                               proj_w, wp, CDIM * CDIM,
                               w1, wf1, CDIM * HIDDEN,
                               w2, wf2, HIDDEN * CDIM);

    ln_kernel<<<lnBlocks, 256>>>(x, g1, be1, xn, 1);

    gemm_tc<EPI_BIAS><<<dim3(QKVDIM / 64, TOK / 128), 256>>>(
        xn, wq, qkv_b, qkvbuf, nullptr, TOK, QKVDIM, CDIM);

    attn_mma_kernel<<<dim3(NWIN, NHEAD), 128>>>(qkvbuf, attnbuf);

    gemm_tc<EPI_PROJ><<<dim3(CDIM / 64, TOK / 128), 256>>>(
        attnbuf, wp, proj_b, xa, nullptr, TOK, CDIM, CDIM);

    ln_kernel<<<lnBlocks, 256>>>(xa, g2, be2, xn, 0);

    gemm_tc<EPI_GELU><<<dim3(HIDDEN / 64, TOK / 128), 256>>>(
        xn, wf1, b1, qkvbuf, nullptr, TOK, HIDDEN, CDIM);

    gemm_tc<EPI_RES><<<dim3(CDIM / 64, TOK / 128), 256>>>(
        qkvbuf, wf2, b2, out, xa, TOK, CDIM, HIDDEN);
}